// round 15
// baseline (speedup 1.0000x reference)
#include <cuda_runtime.h>
#include <cuda_bf16.h>
#include <cuda_fp16.h>
#include <cstdint>

#define MAX_N 100000
#define MAX_E 1600000
#define D 128
#define NB_MAX 128

// Scratch (device globals -- no allocation allowed)
__device__ __half g_hh[(size_t)MAX_N * D];     // 25.6 MB fp16 h
__device__ float g_si[MAX_N];
__device__ float g_sj[MAX_N];
__device__ int   g_cnt[MAX_N];                 // edge hist; countdown restores to 0
__device__ int   g_offp[MAX_N];                // block-local exclusive prefix
__device__ int   g_bsum[NB_MAX];
__device__ int   g_bpre[NB_MAX];
__device__ int   g_d[MAX_E];                   // dst sorted by src (edges only)

__device__ __forceinline__ unsigned h2_to_u32(__half2 h) {
    unsigned u; *reinterpret_cast<__half2*>(&u) = h; return u;
}
__device__ __forceinline__ __half2 u32_to_h2(unsigned u) {
    return *reinterpret_cast<__half2*>(&u);
}

// ---------------------------------------------------------------------------
// Tensor-core GEMM: h = x @ W^T + b via mma.sync m16n8k16 f16f16f32.
// Block tile 128x128, K chunked 2x64. 8 warps: 4 in M x 2 in N.
// (round-7 proven configuration)
// ---------------------------------------------------------------------------
#define KC 64
#define XPITCH 72              // smem row pitch in halves (64 + 8 pad)
#define HPITCH 136             // epilogue pitch (128 + 8 pad)

__global__ __launch_bounds__(256, 2)
void gemm_kernel(const float* __restrict__ x, const float* __restrict__ W,
                 const float* __restrict__ b, const float* __restrict__ Watt,
                 int n) {
    __shared__ __align__(16) char smem_raw[2 * 128 * XPITCH * 2]; // 36864 B
    __half (*xs)[XPITCH] = (__half(*)[XPITCH])smem_raw;
    __half (*ws)[XPITCH] = (__half(*)[XPITCH])(smem_raw + 128 * XPITCH * 2);
    __half (*hs)[HPITCH] = (__half(*)[HPITCH])smem_raw;   // epilogue reuse

    int tid = threadIdx.x;
    int wid = tid >> 5;
    int lane = tid & 31;
    int gid = lane >> 2;
    int tig = lane & 3;
    int wm = wid & 3;
    int wn = wid >> 2;
    int row0 = blockIdx.x * 128;

    float c[2][8][4];
#pragma unroll
    for (int mi = 0; mi < 2; mi++)
#pragma unroll
        for (int ni = 0; ni < 8; ni++)
#pragma unroll
            for (int r = 0; r < 4; r++) c[mi][ni][r] = 0.f;

#pragma unroll
    for (int kk = 0; kk < D; kk += KC) {
#pragma unroll
        for (int r = 0; r < 8; r++) {
            int idx = tid + r * 256;
            int row = idx >> 4;
            int c4 = (idx & 15) * 4;
            float4 v = make_float4(0.f, 0.f, 0.f, 0.f);
            int gr = row0 + row;
            if (gr < n) v = *(const float4*)&x[(size_t)gr * D + kk + c4];
            unsigned p0 = h2_to_u32(__floats2half2_rn(v.x, v.y));
            unsigned p1 = h2_to_u32(__floats2half2_rn(v.z, v.w));
            *(uint2*)&xs[row][c4] = make_uint2(p0, p1);
        }
#pragma unroll
        for (int r = 0; r < 8; r++) {
            int idx = tid + r * 256;
            int cc = idx >> 4;
            int c4 = (idx & 15) * 4;
            float4 v = *(const float4*)&W[(size_t)cc * D + kk + c4];
            unsigned p0 = h2_to_u32(__floats2half2_rn(v.x, v.y));
            unsigned p1 = h2_to_u32(__floats2half2_rn(v.z, v.w));
            *(uint2*)&ws[cc][c4] = make_uint2(p0, p1);
        }
        __syncthreads();

#pragma unroll
        for (int ks = 0; ks < KC / 16; ks++) {
            int kb = ks * 16 + tig * 2;
            unsigned a[2][4];
#pragma unroll
            for (int mi = 0; mi < 2; mi++) {
                int ra = wm * 32 + mi * 16 + gid;
                a[mi][0] = *(const unsigned*)&xs[ra][kb];
                a[mi][1] = *(const unsigned*)&xs[ra + 8][kb];
                a[mi][2] = *(const unsigned*)&xs[ra][kb + 8];
                a[mi][3] = *(const unsigned*)&xs[ra + 8][kb + 8];
            }
#pragma unroll
            for (int ni = 0; ni < 8; ni++) {
                int cb = wn * 64 + ni * 8 + gid;
                unsigned b0 = *(const unsigned*)&ws[cb][kb];
                unsigned b1 = *(const unsigned*)&ws[cb][kb + 8];
#pragma unroll
                for (int mi = 0; mi < 2; mi++) {
                    asm volatile(
                        "mma.sync.aligned.m16n8k16.row.col.f32.f16.f16.f32 "
                        "{%0,%1,%2,%3}, {%4,%5,%6,%7}, {%8,%9}, {%0,%1,%2,%3};"
                        : "+f"(c[mi][ni][0]), "+f"(c[mi][ni][1]),
                          "+f"(c[mi][ni][2]), "+f"(c[mi][ni][3])
                        : "r"(a[mi][0]), "r"(a[mi][1]), "r"(a[mi][2]), "r"(a[mi][3]),
                          "r"(b0), "r"(b1));
                }
            }
        }
        __syncthreads();
    }

    // epilogue pass 1: +bias, fp16, stage in smem
#pragma unroll
    for (int mi = 0; mi < 2; mi++) {
#pragma unroll
        for (int ni = 0; ni < 8; ni++) {
            int rr = wm * 32 + mi * 16 + gid;
            int col = wn * 64 + ni * 8 + tig * 2;
            float bx = __ldg(&b[col]);
            float by = __ldg(&b[col + 1]);
            *(unsigned*)&hs[rr][col] =
                h2_to_u32(__floats2half2_rn(c[mi][ni][0] + bx, c[mi][ni][1] + by));
            *(unsigned*)&hs[rr + 8][col] =
                h2_to_u32(__floats2half2_rn(c[mi][ni][2] + bx, c[mi][ni][3] + by));
        }
    }
    __syncthreads();

    // epilogue pass 2: coalesced store + fused s_i/s_j
    int tx = tid & 15;
    int tyr = tid >> 4;
    float ai_r[8], aj_r[8];
#pragma unroll
    for (int j = 0; j < 8; j++) {
        ai_r[j] = __ldg(&Watt[tx * 8 + j]);
        aj_r[j] = __ldg(&Watt[D + tx * 8 + j]);
    }
#pragma unroll
    for (int it = 0; it < 8; it++) {
        int row = it * 16 + tyr;
        int gr = row0 + row;
        uint4 v = *(const uint4*)&hs[row][tx * 8];
        float2 f0 = __half22float2(u32_to_h2(v.x));
        float2 f1 = __half22float2(u32_to_h2(v.y));
        float2 f2 = __half22float2(u32_to_h2(v.z));
        float2 f3 = __half22float2(u32_to_h2(v.w));
        float psi = f0.x*ai_r[0] + f0.y*ai_r[1] + f1.x*ai_r[2] + f1.y*ai_r[3]
                  + f2.x*ai_r[4] + f2.y*ai_r[5] + f3.x*ai_r[6] + f3.y*ai_r[7];
        float psj = f0.x*aj_r[0] + f0.y*aj_r[1] + f1.x*aj_r[2] + f1.y*aj_r[3]
                  + f2.x*aj_r[4] + f2.y*aj_r[5] + f3.x*aj_r[6] + f3.y*aj_r[7];
#pragma unroll
        for (int o = 8; o; o >>= 1) {
            psi += __shfl_down_sync(0xffffffffu, psi, o, 16);
            psj += __shfl_down_sync(0xffffffffu, psj, o, 16);
        }
        if (gr < n) {
            *(uint4*)&g_hh[(size_t)gr * D + tx * 8] = v;
            if (tx == 0) { g_si[gr] = psi; g_sj[gr] = psj; }
        }
    }
}

// ---------------------------------------------------------------------------
// hist: 4 edges per thread (ILP)
// ---------------------------------------------------------------------------
__global__ void hist_kernel(const int* __restrict__ ei, int E) {
    int t4 = (blockIdx.x * blockDim.x + threadIdx.x) * 4;
    if (t4 + 3 < E) {
        int4 s4 = *(const int4*)&ei[t4];
        atomicAdd(&g_cnt[s4.x], 1);
        atomicAdd(&g_cnt[s4.y], 1);
        atomicAdd(&g_cnt[s4.z], 1);
        atomicAdd(&g_cnt[s4.w], 1);
    } else {
        for (int t = t4; t < E; t++) atomicAdd(&g_cnt[ei[t]], 1);
    }
}

// ---------------------------------------------------------------------------
// exclusive scan over edge counts (self-loops NOT included in slots)
// ---------------------------------------------------------------------------
__global__ void scan1_kernel(int n) {
    __shared__ int sh[1024];
    int i = blockIdx.x * 1024 + threadIdx.x;
    int v = (i < n) ? g_cnt[i] : 0;
    sh[threadIdx.x] = v;
    __syncthreads();
    for (int off = 1; off < 1024; off <<= 1) {
        int t = (threadIdx.x >= off) ? sh[threadIdx.x - off] : 0;
        __syncthreads();
        sh[threadIdx.x] += t;
        __syncthreads();
    }
    if (i < n) g_offp[i] = sh[threadIdx.x] - v;
    if (threadIdx.x == 1023) g_bsum[blockIdx.x] = sh[1023];
}

__global__ void scan2_kernel(int nb) {
    __shared__ int sh[NB_MAX];
    int t = threadIdx.x;
    int v = (t < nb) ? g_bsum[t] : 0;
    sh[t] = v;
    __syncthreads();
    for (int off = 1; off < NB_MAX; off <<= 1) {
        int u = (t >= off) ? sh[t - off] : 0;
        __syncthreads();
        sh[t] += u;
        __syncthreads();
    }
    if (t < nb) g_bpre[t] = sh[t] - v;
}

// ---------------------------------------------------------------------------
// sort: counting-sort scatter of dst by src (score-free -> overlaps GEMM).
// g_cnt counts down to 0 (replay-safe).
// ---------------------------------------------------------------------------
__global__ void sort_kernel(const int* __restrict__ ei, int E) {
    int t = blockIdx.x * blockDim.x + threadIdx.x;
    if (t >= E) return;
    int src = ei[t];
    int dst = ei[E + t];
    int old = atomicAdd(&g_cnt[src], -1);
    g_d[g_offp[src] + g_bpre[src >> 10] + old - 1] = dst;
}

// ---------------------------------------------------------------------------
// aggregate helpers
// ---------------------------------------------------------------------------
// phase A: lane-parallel scoring of one chunk into a smem staging row;
// returns this lane's e contribution.
__device__ __forceinline__ float stageA(uint2* row, int cs, int m,
                                        float si_w, float bb, int lane) {
    float ek = 0.f;
    if (lane < m) {
        int dk = g_d[cs + lane];
        float sc = si_w + g_sj[dk] + bb;
        sc = (sc >= 0.f) ? sc : 0.01f * sc;
        ek = expf(sc);
        row[lane] = make_uint2((unsigned)dk, __float_as_uint(ek));
    }
    return ek;
}

// phase B: gather+accumulate one staged chunk, 8 gathers in flight.
__device__ __forceinline__ void gatherB(float4& acc, const uint2* row, int m,
                                        int lane) {
    int j = 0;
    for (; j + 7 < m; j += 8) {
        uint4 qa = *(const uint4*)&row[j];
        uint4 qb = *(const uint4*)&row[j + 2];
        uint4 qc = *(const uint4*)&row[j + 4];
        uint4 qd = *(const uint4*)&row[j + 6];
        uint2 r0 = *(const uint2*)&g_hh[(size_t)qa.x * D + lane * 4];
        uint2 r1 = *(const uint2*)&g_hh[(size_t)qa.z * D + lane * 4];
        uint2 r2 = *(const uint2*)&g_hh[(size_t)qb.x * D + lane * 4];
        uint2 r3 = *(const uint2*)&g_hh[(size_t)qb.z * D + lane * 4];
        uint2 r4 = *(const uint2*)&g_hh[(size_t)qc.x * D + lane * 4];
        uint2 r5 = *(const uint2*)&g_hh[(size_t)qc.z * D + lane * 4];
        uint2 r6 = *(const uint2*)&g_hh[(size_t)qd.x * D + lane * 4];
        uint2 r7 = *(const uint2*)&g_hh[(size_t)qd.z * D + lane * 4];
        float2 a0, a1;
#define ACC8(r, eu) { \
        float ee = __uint_as_float(eu); \
        a0 = __half22float2(u32_to_h2((r).x)); \
        a1 = __half22float2(u32_to_h2((r).y)); \
        acc.x += ee * a0.x; acc.y += ee * a0.y; \
        acc.z += ee * a1.x; acc.w += ee * a1.y; }
        ACC8(r0, qa.y) ACC8(r1, qa.w) ACC8(r2, qb.y) ACC8(r3, qb.w)
        ACC8(r4, qc.y) ACC8(r5, qc.w) ACC8(r6, qd.y) ACC8(r7, qd.w)
    }
    for (; j + 1 < m; j += 2) {
        uint4 qa = *(const uint4*)&row[j];
        uint2 r0 = *(const uint2*)&g_hh[(size_t)qa.x * D + lane * 4];
        uint2 r1 = *(const uint2*)&g_hh[(size_t)qa.z * D + lane * 4];
        float2 a0, a1;
        ACC8(r0, qa.y) ACC8(r1, qa.w)
    }
    if (j < m) {
        uint2 q = row[j];
        uint2 r0 = *(const uint2*)&g_hh[(size_t)q.x * D + lane * 4];
        float2 a0, a1;
        ACC8(r0, q.y)
#undef ACC8
    }
}

// ---------------------------------------------------------------------------
// aggregation: warp per TWO nodes. Phase A for both first chunks issued
// back-to-back (2 independent latency chains in flight), then phase B
// (8-wide gathers) per node. Self-loops analytic. Fused normalize + ELU.
// ---------------------------------------------------------------------------
__global__ __launch_bounds__(256)
void aggregate_kernel(float* __restrict__ out, const float* __restrict__ batt,
                      int n, int E) {
    __shared__ __align__(16) uint2 sde[8][2][32];   // 4 KB staging
    int wl = threadIdx.x >> 5;
    int gw = (blockIdx.x * blockDim.x + threadIdx.x) >> 5;
    int lane = threadIdx.x & 31;
    int w0 = gw * 2;
    if (w0 >= n) return;
    int w1 = w0 + 1;
    bool has1 = (w1 < n);
    float bb = __ldg(batt);

    int s0 = g_offp[w0] + g_bpre[w0 >> 10];
    int e0 = (w0 + 1 < n) ? (g_offp[w0 + 1] + g_bpre[(w0 + 1) >> 10]) : E;
    int s1 = e0;                         // segments are contiguous
    int e1 = has1 ? ((w1 + 1 < n) ? (g_offp[w1 + 1] + g_bpre[(w1 + 1) >> 10]) : E)
                  : e0;

    float si0 = g_si[w0];
    float si1 = has1 ? g_si[w1] : 0.f;

    // self-loop terms (independent chains)
    float sc0 = si0 + g_sj[w0] + bb;
    sc0 = (sc0 >= 0.f) ? sc0 : 0.01f * sc0;
    float es0 = expf(sc0);
    float es1 = 0.f;
    if (has1) {
        float sc1 = si1 + g_sj[w1] + bb;
        sc1 = (sc1 >= 0.f) ? sc1 : 0.01f * sc1;
        es1 = expf(sc1);
    }

    float4 acc0, acc1 = make_float4(0.f, 0.f, 0.f, 0.f);
    {
        uint2 rw = *(const uint2*)&g_hh[(size_t)w0 * D + lane * 4];
        float2 a0 = __half22float2(u32_to_h2(rw.x));
        float2 a1 = __half22float2(u32_to_h2(rw.y));
        acc0 = make_float4(es0 * a0.x, es0 * a0.y, es0 * a1.x, es0 * a1.y);
    }
    if (has1) {
        uint2 rw = *(const uint2*)&g_hh[(size_t)w1 * D + lane * 4];
        float2 a0 = __half22float2(u32_to_h2(rw.x));
        float2 a1 = __half22float2(u32_to_h2(rw.y));
        acc1 = make_float4(es1 * a0.x, es1 * a0.y, es1 * a1.x, es1 * a1.y);
    }

    // phase A for BOTH first chunks (two independent latency chains)
    int m0 = e0 - s0; if (m0 > 32) m0 = 32;
    int m1 = has1 ? (e1 - s1) : 0; if (m1 > 32) m1 = 32;
    float denp0 = stageA(sde[wl][0], s0, m0, si0, bb, lane);
    float denp1 = (m1 > 0) ? stageA(sde[wl][1], s1, m1, si1, bb, lane) : 0.f;
    __syncwarp();

    // phase B node0 + remaining chunks
    gatherB(acc0, sde[wl][0], m0, lane);
    for (int cs = s0 + 32; cs < e0; cs += 32) {
        int m = e0 - cs; if (m > 32) m = 32;
        __syncwarp();
        denp0 += stageA(sde[wl][0], cs, m, si0, bb, lane);
        __syncwarp();
        gatherB(acc0, sde[wl][0], m, lane);
    }
    // phase B node1 + remaining chunks
    if (has1) {
        gatherB(acc1, sde[wl][1], m1, lane);
        for (int cs = s1 + 32; cs < e1; cs += 32) {
            int m = e1 - cs; if (m > 32) m = 32;
            __syncwarp();
            denp1 += stageA(sde[wl][1], cs, m, si1, bb, lane);
            __syncwarp();
            gatherB(acc1, sde[wl][1], m, lane);
        }
    }

    // lane reductions + finalize (both nodes)
    float den0 = denp0, den1 = denp1;
#pragma unroll
    for (int o = 16; o; o >>= 1) {
        den0 += __shfl_xor_sync(0xffffffffu, den0, o);
        den1 += __shfl_xor_sync(0xffffffffu, den1, o);
    }
    den0 += es0;
    {
        float inv = 1.f / den0;
        float ox = acc0.x * inv, oy = acc0.y * inv;
        float oz = acc0.z * inv, ow = acc0.w * inv;
        ox = (ox > 0.f) ? ox : expm1f(ox);
        oy = (oy > 0.f) ? oy : expm1f(oy);
        oz = (oz > 0.f) ? oz : expm1f(oz);
        ow = (ow > 0.f) ? ow : expm1f(ow);
        float* p = &out[(size_t)w0 * D + lane * 4];
        asm volatile("st.global.cs.v4.f32 [%0], {%1,%2,%3,%4};"
                     :: "l"(p), "f"(ox), "f"(oy), "f"(oz), "f"(ow) : "memory");
    }
    if (has1) {
        den1 += es1;
        float inv = 1.f / den1;
        float ox = acc1.x * inv, oy = acc1.y * inv;
        float oz = acc1.z * inv, ow = acc1.w * inv;
        ox = (ox > 0.f) ? ox : expm1f(ox);
        oy = (oy > 0.f) ? oy : expm1f(oy);
        oz = (oz > 0.f) ? oz : expm1f(oz);
        ow = (ow > 0.f) ? ow : expm1f(ow);
        float* p = &out[(size_t)w1 * D + lane * 4];
        asm volatile("st.global.cs.v4.f32 [%0], {%1,%2,%3,%4};"
                     :: "l"(p), "f"(ox), "f"(oy), "f"(oz), "f"(ow) : "memory");
    }
}

// ---------------------------------------------------------------------------
extern "C" void kernel_launch(void* const* d_in, const int* in_sizes, int n_in,
                              void* d_out, int out_size) {
    const float* x    = (const float*)d_in[0];
    const int*   ei   = (const int*)  d_in[1];
    const float* W    = (const float*)d_in[2];
    const float* b    = (const float*)d_in[3];
    const float* Watt = (const float*)d_in[4];
    const float* batt = (const float*)d_in[5];
    float* out = (float*)d_out;

    int n = in_sizes[0] / D;
    int E = in_sizes[1] / 2;
    int nb = (n + 1023) / 1024;
    int e4 = (E + 3) / 4;
    int npair = (n + 1) / 2;

    // side stream + events for fork/join inside graph capture (created once)
    static cudaStream_t s1 = nullptr;
    static cudaEvent_t ev_fork = nullptr, ev_join = nullptr;
    if (s1 == nullptr) {
        cudaStreamCreateWithFlags(&s1, cudaStreamNonBlocking);
        cudaEventCreateWithFlags(&ev_fork, cudaEventDisableTiming);
        cudaEventCreateWithFlags(&ev_join, cudaEventDisableTiming);
    }

    // fork: FULL edge pipeline (hist -> scans -> sort) concurrent with GEMM
    cudaEventRecord(ev_fork, 0);
    cudaStreamWaitEvent(s1, ev_fork, 0);
    hist_kernel<<<(e4 + 255) / 256, 256, 0, s1>>>(ei, E);
    scan1_kernel<<<nb, 1024, 0, s1>>>(n);
    scan2_kernel<<<1, NB_MAX, 0, s1>>>(nb);
    sort_kernel<<<(E + 255) / 256, 256, 0, s1>>>(ei, E);
    cudaEventRecord(ev_join, s1);

    gemm_kernel<<<(n + 127) / 128, 256>>>(x, W, b, Watt, n);

    cudaStreamWaitEvent(0, ev_join, 0);
    aggregate_kernel<<<((long long)npair * 32 + 255) / 256, 256>>>(out, batt, n, E);
}

// round 16
// speedup vs baseline: 1.0117x; 1.0117x over previous
#include <cuda_runtime.h>
#include <cuda_bf16.h>
#include <cuda_fp16.h>
#include <cstdint>

#define MAX_N 100000
#define MAX_E 1600000
#define D 128
#define NB_MAX 128

// Scratch (device globals -- no allocation allowed)
__device__ __half g_hh[(size_t)MAX_N * D];     // 25.6 MB fp16 h
__device__ float g_si[MAX_N];
__device__ float g_sj[MAX_N];
__device__ int   g_cnt[MAX_N];                 // edge hist; countdown restores to 0
__device__ int   g_offp[MAX_N];                // block-local exclusive prefix
__device__ int   g_bsum[NB_MAX];
__device__ int   g_bpre[NB_MAX];
__device__ int   g_d[MAX_E];                   // dst sorted by src (edges only)

__device__ __forceinline__ unsigned h2_to_u32(__half2 h) {
    unsigned u; *reinterpret_cast<__half2*>(&u) = h; return u;
}
__device__ __forceinline__ __half2 u32_to_h2(unsigned u) {
    return *reinterpret_cast<__half2*>(&u);
}

// ---------------------------------------------------------------------------
// Tensor-core GEMM: h = x @ W^T + b via mma.sync m16n8k16 f16f16f32.
// Block tile 128x128, K chunked 2x64. 8 warps: 4 in M x 2 in N.
// (round-7 proven configuration)
// ---------------------------------------------------------------------------
#define KC 64
#define XPITCH 72              // smem row pitch in halves (64 + 8 pad)
#define HPITCH 136             // epilogue pitch (128 + 8 pad)

__global__ __launch_bounds__(256, 2)
void gemm_kernel(const float* __restrict__ x, const float* __restrict__ W,
                 const float* __restrict__ b, const float* __restrict__ Watt,
                 int n) {
    __shared__ __align__(16) char smem_raw[2 * 128 * XPITCH * 2]; // 36864 B
    __half (*xs)[XPITCH] = (__half(*)[XPITCH])smem_raw;
    __half (*ws)[XPITCH] = (__half(*)[XPITCH])(smem_raw + 128 * XPITCH * 2);
    __half (*hs)[HPITCH] = (__half(*)[HPITCH])smem_raw;   // epilogue reuse

    int tid = threadIdx.x;
    int wid = tid >> 5;
    int lane = tid & 31;
    int gid = lane >> 2;
    int tig = lane & 3;
    int wm = wid & 3;
    int wn = wid >> 2;
    int row0 = blockIdx.x * 128;

    float c[2][8][4];
#pragma unroll
    for (int mi = 0; mi < 2; mi++)
#pragma unroll
        for (int ni = 0; ni < 8; ni++)
#pragma unroll
            for (int r = 0; r < 4; r++) c[mi][ni][r] = 0.f;

#pragma unroll
    for (int kk = 0; kk < D; kk += KC) {
#pragma unroll
        for (int r = 0; r < 8; r++) {
            int idx = tid + r * 256;
            int row = idx >> 4;
            int c4 = (idx & 15) * 4;
            float4 v = make_float4(0.f, 0.f, 0.f, 0.f);
            int gr = row0 + row;
            if (gr < n) v = *(const float4*)&x[(size_t)gr * D + kk + c4];
            unsigned p0 = h2_to_u32(__floats2half2_rn(v.x, v.y));
            unsigned p1 = h2_to_u32(__floats2half2_rn(v.z, v.w));
            *(uint2*)&xs[row][c4] = make_uint2(p0, p1);
        }
#pragma unroll
        for (int r = 0; r < 8; r++) {
            int idx = tid + r * 256;
            int cc = idx >> 4;
            int c4 = (idx & 15) * 4;
            float4 v = *(const float4*)&W[(size_t)cc * D + kk + c4];
            unsigned p0 = h2_to_u32(__floats2half2_rn(v.x, v.y));
            unsigned p1 = h2_to_u32(__floats2half2_rn(v.z, v.w));
            *(uint2*)&ws[cc][c4] = make_uint2(p0, p1);
        }
        __syncthreads();

#pragma unroll
        for (int ks = 0; ks < KC / 16; ks++) {
            int kb = ks * 16 + tig * 2;
            unsigned a[2][4];
#pragma unroll
            for (int mi = 0; mi < 2; mi++) {
                int ra = wm * 32 + mi * 16 + gid;
                a[mi][0] = *(const unsigned*)&xs[ra][kb];
                a[mi][1] = *(const unsigned*)&xs[ra + 8][kb];
                a[mi][2] = *(const unsigned*)&xs[ra][kb + 8];
                a[mi][3] = *(const unsigned*)&xs[ra + 8][kb + 8];
            }
#pragma unroll
            for (int ni = 0; ni < 8; ni++) {
                int cb = wn * 64 + ni * 8 + gid;
                unsigned b0 = *(const unsigned*)&ws[cb][kb];
                unsigned b1 = *(const unsigned*)&ws[cb][kb + 8];
#pragma unroll
                for (int mi = 0; mi < 2; mi++) {
                    asm volatile(
                        "mma.sync.aligned.m16n8k16.row.col.f32.f16.f16.f32 "
                        "{%0,%1,%2,%3}, {%4,%5,%6,%7}, {%8,%9}, {%0,%1,%2,%3};"
                        : "+f"(c[mi][ni][0]), "+f"(c[mi][ni][1]),
                          "+f"(c[mi][ni][2]), "+f"(c[mi][ni][3])
                        : "r"(a[mi][0]), "r"(a[mi][1]), "r"(a[mi][2]), "r"(a[mi][3]),
                          "r"(b0), "r"(b1));
                }
            }
        }
        __syncthreads();
    }

    // epilogue pass 1: +bias, fp16, stage in smem
#pragma unroll
    for (int mi = 0; mi < 2; mi++) {
#pragma unroll
        for (int ni = 0; ni < 8; ni++) {
            int rr = wm * 32 + mi * 16 + gid;
            int col = wn * 64 + ni * 8 + tig * 2;
            float bx = __ldg(&b[col]);
            float by = __ldg(&b[col + 1]);
            *(unsigned*)&hs[rr][col] =
                h2_to_u32(__floats2half2_rn(c[mi][ni][0] + bx, c[mi][ni][1] + by));
            *(unsigned*)&hs[rr + 8][col] =
                h2_to_u32(__floats2half2_rn(c[mi][ni][2] + bx, c[mi][ni][3] + by));
        }
    }
    __syncthreads();

    // epilogue pass 2: coalesced store + fused s_i/s_j
    int tx = tid & 15;
    int tyr = tid >> 4;
    float ai_r[8], aj_r[8];
#pragma unroll
    for (int j = 0; j < 8; j++) {
        ai_r[j] = __ldg(&Watt[tx * 8 + j]);
        aj_r[j] = __ldg(&Watt[D + tx * 8 + j]);
    }
#pragma unroll
    for (int it = 0; it < 8; it++) {
        int row = it * 16 + tyr;
        int gr = row0 + row;
        uint4 v = *(const uint4*)&hs[row][tx * 8];
        float2 f0 = __half22float2(u32_to_h2(v.x));
        float2 f1 = __half22float2(u32_to_h2(v.y));
        float2 f2 = __half22float2(u32_to_h2(v.z));
        float2 f3 = __half22float2(u32_to_h2(v.w));
        float psi = f0.x*ai_r[0] + f0.y*ai_r[1] + f1.x*ai_r[2] + f1.y*ai_r[3]
                  + f2.x*ai_r[4] + f2.y*ai_r[5] + f3.x*ai_r[6] + f3.y*ai_r[7];
        float psj = f0.x*aj_r[0] + f0.y*aj_r[1] + f1.x*aj_r[2] + f1.y*aj_r[3]
                  + f2.x*aj_r[4] + f2.y*aj_r[5] + f3.x*aj_r[6] + f3.y*aj_r[7];
#pragma unroll
        for (int o = 8; o; o >>= 1) {
            psi += __shfl_down_sync(0xffffffffu, psi, o, 16);
            psj += __shfl_down_sync(0xffffffffu, psj, o, 16);
        }
        if (gr < n) {
            *(uint4*)&g_hh[(size_t)gr * D + tx * 8] = v;
            if (tx == 0) { g_si[gr] = psi; g_sj[gr] = psj; }
        }
    }
}

// ---------------------------------------------------------------------------
// hist: 4 edges per thread (ILP)
// ---------------------------------------------------------------------------
__global__ void hist_kernel(const int* __restrict__ ei, int E) {
    int t4 = (blockIdx.x * blockDim.x + threadIdx.x) * 4;
    if (t4 + 3 < E) {
        int4 s4 = __ldg((const int4*)&ei[t4]);
        atomicAdd(&g_cnt[s4.x], 1);
        atomicAdd(&g_cnt[s4.y], 1);
        atomicAdd(&g_cnt[s4.z], 1);
        atomicAdd(&g_cnt[s4.w], 1);
    } else {
        for (int t = t4; t < E; t++) atomicAdd(&g_cnt[ei[t]], 1);
    }
}

// ---------------------------------------------------------------------------
// exclusive scan over edge counts (self-loops NOT included in slots)
// ---------------------------------------------------------------------------
__global__ void scan1_kernel(int n) {
    __shared__ int sh[1024];
    int i = blockIdx.x * 1024 + threadIdx.x;
    int v = (i < n) ? g_cnt[i] : 0;
    sh[threadIdx.x] = v;
    __syncthreads();
    for (int off = 1; off < 1024; off <<= 1) {
        int t = (threadIdx.x >= off) ? sh[threadIdx.x - off] : 0;
        __syncthreads();
        sh[threadIdx.x] += t;
        __syncthreads();
    }
    if (i < n) g_offp[i] = sh[threadIdx.x] - v;
    if (threadIdx.x == 1023) g_bsum[blockIdx.x] = sh[1023];
}

__global__ void scan2_kernel(int nb) {
    __shared__ int sh[NB_MAX];
    int t = threadIdx.x;
    int v = (t < nb) ? g_bsum[t] : 0;
    sh[t] = v;
    __syncthreads();
    for (int off = 1; off < NB_MAX; off <<= 1) {
        int u = (t >= off) ? sh[t - off] : 0;
        __syncthreads();
        sh[t] += u;
        __syncthreads();
    }
    if (t < nb) g_bpre[t] = sh[t] - v;
}

// ---------------------------------------------------------------------------
// sort: counting-sort scatter of dst by src (score-free -> overlaps GEMM).
// Scattered store uses .cs to avoid evicting g_hh while the GEMM writes it.
// g_cnt counts down to 0 (replay-safe).
// ---------------------------------------------------------------------------
__global__ void sort_kernel(const int* __restrict__ ei, int E) {
    int t = blockIdx.x * blockDim.x + threadIdx.x;
    if (t >= E) return;
    int src = __ldg(&ei[t]);
    int dst = __ldg(&ei[E + t]);
    int old = atomicAdd(&g_cnt[src], -1);
    int* p = &g_d[g_offp[src] + g_bpre[src >> 10] + old - 1];
    asm volatile("st.global.cs.u32 [%0], %1;" :: "l"(p), "r"(dst) : "memory");
}

// ---------------------------------------------------------------------------
// aggregate helpers (round-14 proven form)
// ---------------------------------------------------------------------------
// phase A: lane-parallel scoring of one chunk into a smem staging row;
// returns this lane's e contribution. g_d is read-once -> .cs.
__device__ __forceinline__ float stageA(uint2* row, int cs, int m,
                                        float si_w, float bb, int lane) {
    float ek = 0.f;
    if (lane < m) {
        int dk;
        asm volatile("ld.global.cs.u32 %0, [%1];"
                     : "=r"(dk) : "l"(&g_d[cs + lane]));
        float sc = si_w + __ldg(&g_sj[dk]) + bb;
        sc = (sc >= 0.f) ? sc : 0.01f * sc;
        ek = expf(sc);
        row[lane] = make_uint2((unsigned)dk, __float_as_uint(ek));
    }
    return ek;
}

// phase B: gather+accumulate one staged chunk, 8 gathers in flight.
__device__ __forceinline__ void gatherB(float4& acc, const uint2* row, int m,
                                        int lane) {
    int j = 0;
    for (; j + 7 < m; j += 8) {
        uint4 qa = *(const uint4*)&row[j];
        uint4 qb = *(const uint4*)&row[j + 2];
        uint4 qc = *(const uint4*)&row[j + 4];
        uint4 qd = *(const uint4*)&row[j + 6];
        uint2 r0 = *(const uint2*)&g_hh[(size_t)qa.x * D + lane * 4];
        uint2 r1 = *(const uint2*)&g_hh[(size_t)qa.z * D + lane * 4];
        uint2 r2 = *(const uint2*)&g_hh[(size_t)qb.x * D + lane * 4];
        uint2 r3 = *(const uint2*)&g_hh[(size_t)qb.z * D + lane * 4];
        uint2 r4 = *(const uint2*)&g_hh[(size_t)qc.x * D + lane * 4];
        uint2 r5 = *(const uint2*)&g_hh[(size_t)qc.z * D + lane * 4];
        uint2 r6 = *(const uint2*)&g_hh[(size_t)qd.x * D + lane * 4];
        uint2 r7 = *(const uint2*)&g_hh[(size_t)qd.z * D + lane * 4];
        float2 a0, a1;
#define ACC8(r, eu) { \
        float ee = __uint_as_float(eu); \
        a0 = __half22float2(u32_to_h2((r).x)); \
        a1 = __half22float2(u32_to_h2((r).y)); \
        acc.x += ee * a0.x; acc.y += ee * a0.y; \
        acc.z += ee * a1.x; acc.w += ee * a1.y; }
        ACC8(r0, qa.y) ACC8(r1, qa.w) ACC8(r2, qb.y) ACC8(r3, qb.w)
        ACC8(r4, qc.y) ACC8(r5, qc.w) ACC8(r6, qd.y) ACC8(r7, qd.w)
    }
    for (; j + 1 < m; j += 2) {
        uint4 qa = *(const uint4*)&row[j];
        uint2 r0 = *(const uint2*)&g_hh[(size_t)qa.x * D + lane * 4];
        uint2 r1 = *(const uint2*)&g_hh[(size_t)qa.z * D + lane * 4];
        float2 a0, a1;
        ACC8(r0, qa.y) ACC8(r1, qa.w)
    }
    if (j < m) {
        uint2 q = row[j];
        uint2 r0 = *(const uint2*)&g_hh[(size_t)q.x * D + lane * 4];
        float2 a0, a1;
        ACC8(r0, q.y)
#undef ACC8
    }
}

// ---------------------------------------------------------------------------
// aggregation: warp per src node, inline scoring with SMEM staging
// (round-14 proven form), 512-thread blocks. Fused normalize + ELU.
// ---------------------------------------------------------------------------
__global__ __launch_bounds__(512)
void aggregate_kernel(float* __restrict__ out, const float* __restrict__ batt,
                      int n, int E) {
    __shared__ __align__(16) uint2 sde[16][32];  // per-warp staging (4 KB)
    int wl = threadIdx.x >> 5;
    int w = (blockIdx.x * blockDim.x + threadIdx.x) >> 5;
    int lane = threadIdx.x & 31;
    if (w >= n) return;
    int s = g_offp[w] + g_bpre[w >> 10];
    int e = (w + 1 < n) ? (g_offp[w + 1] + g_bpre[(w + 1) >> 10]) : E;

    float bb = __ldg(batt);
    float si_w = g_si[w];

    // self-loop term
    float scs = si_w + g_sj[w] + bb;
    scs = (scs >= 0.f) ? scs : 0.01f * scs;
    float es = expf(scs);

    float4 acc;
    {
        uint2 rw = *(const uint2*)&g_hh[(size_t)w * D + lane * 4];
        float2 a0 = __half22float2(u32_to_h2(rw.x));
        float2 a1 = __half22float2(u32_to_h2(rw.y));
        acc = make_float4(es * a0.x, es * a0.y, es * a1.x, es * a1.y);
    }
    float denp = 0.f;

    for (int cs = s; cs < e; cs += 32) {
        int m = e - cs; if (m > 32) m = 32;
        denp += stageA(sde[wl], cs, m, si_w, bb, lane);
        __syncwarp();
        gatherB(acc, sde[wl], m, lane);
        __syncwarp();
    }

    float den = denp;
#pragma unroll
    for (int o = 16; o; o >>= 1) den += __shfl_xor_sync(0xffffffffu, den, o);
    den += es;

    float inv = 1.f / den;
    float4 o;
    o.x = acc.x * inv; o.y = acc.y * inv; o.z = acc.z * inv; o.w = acc.w * inv;
    o.x = (o.x > 0.f) ? o.x : expm1f(o.x);
    o.y = (o.y > 0.f) ? o.y : expm1f(o.y);
    o.z = (o.z > 0.f) ? o.z : expm1f(o.z);
    o.w = (o.w > 0.f) ? o.w : expm1f(o.w);
    float* p = &out[(size_t)w * D + lane * 4];
    asm volatile("st.global.cs.v4.f32 [%0], {%1,%2,%3,%4};"
                 :: "l"(p), "f"(o.x), "f"(o.y), "f"(o.z), "f"(o.w) : "memory");
}

// ---------------------------------------------------------------------------
extern "C" void kernel_launch(void* const* d_in, const int* in_sizes, int n_in,
                              void* d_out, int out_size) {
    const float* x    = (const float*)d_in[0];
    const int*   ei   = (const int*)  d_in[1];
    const float* W    = (const float*)d_in[2];
    const float* b    = (const float*)d_in[3];
    const float* Watt = (const float*)d_in[4];
    const float* batt = (const float*)d_in[5];
    float* out = (float*)d_out;

    int n = in_sizes[0] / D;
    int E = in_sizes[1] / 2;
    int nb = (n + 1023) / 1024;
    int e4 = (E + 3) / 4;

    // side stream + events for fork/join inside graph capture (created once)
    static cudaStream_t s1 = nullptr;
    static cudaEvent_t ev_fork = nullptr, ev_join = nullptr;
    if (s1 == nullptr) {
        cudaStreamCreateWithFlags(&s1, cudaStreamNonBlocking);
        cudaEventCreateWithFlags(&ev_fork, cudaEventDisableTiming);
        cudaEventCreateWithFlags(&ev_join, cudaEventDisableTiming);
    }

    // fork: FULL edge pipeline (hist -> scans -> sort) concurrent with GEMM
    cudaEventRecord(ev_fork, 0);
    cudaStreamWaitEvent(s1, ev_fork, 0);
    hist_kernel<<<(e4 + 255) / 256, 256, 0, s1>>>(ei, E);
    scan1_kernel<<<nb, 1024, 0, s1>>>(n);
    scan2_kernel<<<1, NB_MAX, 0, s1>>>(nb);
    sort_kernel<<<(E + 255) / 256, 256, 0, s1>>>(ei, E);
    cudaEventRecord(ev_join, s1);

    gemm_kernel<<<(n + 127) / 128, 256>>>(x, W, b, Watt, n);

    cudaStreamWaitEvent(0, ev_join, 0);
    aggregate_kernel<<<((long long)n * 32 + 511) / 512, 512>>>(out, batt, n, E);
}